// round 12
// baseline (speedup 1.0000x reference)
#include <cuda_runtime.h>

// PolyphaseDiff: resample_poly(x, up=3, down=2), 129-tap FIR.
// out[j] = sum_c a_pf[c] * x[i0-42+c], t=64+2j, pf=t%3, i0=t/3, a_pf[c]=3h[pf+126-3c].
//
// Compute core (validated R5-R11): one f32x2 loop for all 3 output classes,
//   acc[r] += T[p][k] * tq[8u + r + k], k=0..21,
// tile as u64 pairs in padded smem (9u + immediate addressing, LDS.64
// conflict-free), taps phase-folded per class, staged conflict-free STS +
// float4 coalesced stores.
//
// R12: attack the per-tile serial latency chain (the invariant ~15us across
// occ 36-60% says critical path, not throughput):
//  (a) cp.async (LDGSTS) double-buffered tile loads -- async engine fills the
//      next buffer during compute; removes the LDG->reg->STS commit stall and
//      ~10 registers. Interior tiles unguarded; 2 edge tiles use scalar path.
//  (b) split epilogue barrier: warp triples {0,1,2} / {3,4,5} produce and
//      store disjoint sh_out halves -> bar.sync 96 instead of full block.

#define RR 8                 // outputs per thread
#define NP 22                // tap pairs per class
#define LOOKAHEAD 8          // window pairs preloaded (1-step stagger)
#define THREADS 192          // 6 warps: warp w -> class w%3
#define NOUT_BLK 1536        // outputs per tile = 3 * 64 * RR
#define TPB 2                // tiles per block
#define TQ 536               // u64 pairs per tile
#define TQ_ALLOC (TQ + TQ / 8 + 2)
#define TILE_F (TQ * 2)      // 1072 floats per tile

typedef unsigned long long u64;

#define FMA_X2(d, a, b, c) \
    asm("fma.rn.f32x2 %0, %1, %2, %3;" : "=l"(d) : "l"(a), "l"(b), "l"(c))
#define PACK_X2(d, lo, hi) \
    asm("mov.b64 %0, {%1, %2};" : "=l"(d) : "f"(lo), "f"(hi))
#define UNPACK_X2(lo, hi, s) \
    asm("mov.b64 {%0, %1}, %2;" : "=f"(lo), "=f"(hi) : "l"(s))

#define CP_ASYNC4(dst_u32, src_ptr) \
    asm volatile("cp.async.ca.shared.global [%0], [%1], 4;" \
                 :: "r"(dst_u32), "l"(src_ptr))
#define CP_COMMIT() asm volatile("cp.async.commit_group;" ::: "memory")
#define CP_WAIT0()  asm volatile("cp.async.wait_group 0;" ::: "memory")
#define BAR_HALF(id) \
    asm volatile("bar.sync %0, 96;" :: "r"(id) : "memory")

__device__ __forceinline__ int SP(int i) { return i + (i >> 3); }

// Load tile tt into buf. Interior tiles: 4B cp.async (padded layout via
// f + 2*(f>>4), which equals the pair layout since (2i+b)>>4 == i>>3).
// Edge tiles (tt==0 or top): guarded scalar fallback, plain STS.
__device__ __forceinline__ void load_tile(u64* buf, const float* __restrict__ x,
                                          int tt, int tid, int N)
{
    const int IB = 1024 * tt - 21;
    if (IB >= 0 && IB + TILE_F <= N) {
        unsigned base = (unsigned)__cvta_generic_to_shared(buf);
        #pragma unroll
        for (int q = 0; q < 6; ++q) {
            int f = tid + q * THREADS;
            if (f < TILE_F) {
                unsigned dst = base + 4u * (unsigned)(f + 2 * (f >> 4));
                CP_ASYNC4(dst, x + IB + f);
            }
        }
    } else {
        for (int i = tid; i < TQ; i += THREADS) {
            int g0 = IB + 2 * i, g1 = g0 + 1;
            float lo = (g0 >= 0 && g0 < N) ? x[g0] : 0.0f;
            float hi = (g1 >= 0 && g1 < N) ? x[g1] : 0.0f;
            u64 d; PACK_X2(d, lo, hi);
            buf[SP(i)] = d;
        }
    }
}

__global__ __launch_bounds__(THREADS, 7)
void poly_resample_kernel(const float* __restrict__ x,
                          const float* __restrict__ h,
                          float* __restrict__ out,
                          int N, int n_out, int n_tiles)
{
    __shared__ __align__(16) u64   sh2[2][TQ_ALLOC];   // double-buffered tile
    __shared__ __align__(16) u64   sh_t[3 * NP];       // tap pairs per class
    __shared__ __align__(16) float sh_out[NOUT_BLK];   // output staging

    const int tid = threadIdx.x;

    // ---- pack taps: class p uses filter phase pf = (1+2p)%3 ----
    if (tid < 3 * NP) {
        int p = tid / NP, k = tid % NP;
        int pf = (1 + 2 * p) % 3;             // {1,0,2}
        float lo, hi;
        if (p == 0) {                         // (a[2k], a[2k+1]), zero tail
            lo = 3.0f * h[127 - 6 * k];
            hi = (k < 21) ? 3.0f * h[124 - 6 * k] : 0.0f;
        } else if (k == 0) {                  // head pair (0, a[0])
            lo = 0.0f;
            hi = 3.0f * h[pf + 126];
        } else {                              // (a[2k-1], a[2k])
            lo = 3.0f * h[pf + 129 - 6 * k];
            hi = 3.0f * h[pf + 126 - 6 * k];
        }
        u64 d; PACK_X2(d, lo, hi);
        sh_t[tid] = d;
    }

    const int t0 = blockIdx.x * TPB;
    const int ntloc = min(TPB, n_tiles - t0);

    // ---- prologue: tile t0 into buffer 0 ----
    load_tile(sh2[0], x, t0, tid, N);
    CP_COMMIT(); CP_WAIT0();
    __syncthreads();

    const int wid  = tid >> 5;
    const int lane = tid & 31;
    const int p    = wid % 3;                 // class = j mod 3 (uniform/warp)
    const int u    = (wid / 3) * 32 + lane;   // 0..63 within class
    const int half = (tid < 96) ? 0 : 1;      // warp triple
    const u64* __restrict__ T = sh_t + p * NP;

    int cur = 0;
    for (int t = 0; t < ntloc; ++t) {
        const int tt = t0 + t;
        const bool hasnext = (t + 1 < ntloc);

        // async-fill next buffer while this tile computes
        if (hasnext)
            load_tile(sh2[cur ^ 1], x, tt + 1, tid, N);
        CP_COMMIT();

        // ---- compute tile tt from sh2[cur] ----
        const u64* __restrict__ wb = &sh2[cur][0] + 9 * u;

        u64 wp[29];
        #pragma unroll
        for (int m = 0; m < LOOKAHEAD; ++m)
            wp[m] = wb[m + (m >> 3)];

        u64 acc[RR];
        #pragma unroll
        for (int r = 0; r < RR; ++r) acc[r] = 0ull;

        #pragma unroll
        for (int k = 0; k < NP; ++k) {
            if (k + LOOKAHEAD < 29) {
                const int m = k + LOOKAHEAD;
                wp[m] = wb[m + (m >> 3)];
            }
            const u64 tp = T[k];               // uniform -> LDS.64 broadcast
            #pragma unroll
            for (int r = 0; r < RR; ++r)
                FMA_X2(acc[r], tp, wp[k + r], acc[r]);
        }

        // stage outputs (stride-3 STS conflict-free); each warp triple owns
        // a disjoint 768-float half of sh_out -> half-block barrier suffices
        const int q0 = u * RR;
        #pragma unroll
        for (int r = 0; r < RR; ++r) {
            float e, o; UNPACK_X2(e, o, acc[r]);
            sh_out[3 * (q0 + r) + p] = e + o;
        }
        if (half == 0) BAR_HALF(1); else BAR_HALF(2);

        // coalesced float4 store of this half's 768 outputs
        const int Jb = tt * NOUT_BLK;
        if (Jb + NOUT_BLK <= n_out) {
            const float4* __restrict__ s4 = (const float4*)sh_out;
            float4* __restrict__ o4 = (float4*)(out + Jb);
            const int tb = (half == 0) ? tid : (96 + (tid - 96));  // tid
            #pragma unroll
            for (int q = 0; q < 2; ++q)
                o4[tb + q * 96 + half * 96] = s4[tb + q * 96 + half * 96];
        } else {
            const int m0 = half * 768;
            const int th = tid - half * 96;
            for (int m = th; m < 768; m += 96) {
                int j = Jb + m0 + m;
                if (j < n_out) out[j] = sh_out[m0 + m];
            }
        }

        // drain async fill, publish next buffer
        if (hasnext) {
            CP_WAIT0();
            __syncthreads();
        }
        cur ^= 1;
    }
}

extern "C" void kernel_launch(void* const* d_in, const int* in_sizes, int n_in,
                              void* d_out, int out_size)
{
    const float* x = (const float*)d_in[0];
    const float* h = (const float*)d_in[1];
    float* out = (float*)d_out;

    const int N = in_sizes[0];
    const int n_out = out_size;
    const int n_tiles = (n_out + NOUT_BLK - 1) / NOUT_BLK;       // 2048
    const int grid = (n_tiles + TPB - 1) / TPB;                  // 1024

    poly_resample_kernel<<<grid, THREADS>>>(x, h, out, N, n_out, n_tiles);
}